// round 8
// baseline (speedup 1.0000x reference)
#include <cuda_runtime.h>
#include <cstdint>
#include <math.h>

#define BATCH 8192
#define SDIM  268
#define HDIM  1024
#define RB    8
#define ADIM  256
#define ZDIM  8
#define EDIM  4
#define KXP   320   /* 270 padded to multiple of 64 */

#define CDIV(a,b) (((a)+(b)-1)/(b))
#define EPI_NONE 0
#define EPI_RELU 1
#define EPI_TANH 2

// GEMM tiling: CTA 128x128, 8 warps (2M x 4N), warp tile 64x32, K chunk 64
#define KC     64
#define RSTR   80               /* 64B row + 16B pad: conflict-free ldmatrix */
#define LV     10240            /* one level = 128 rows * 80B */
#define STG_SZ 40960            /* A0,A1,B0,B1 levels */
#define NSTAGE 4
#define SMEM_DYN (NSTAGE*STG_SZ)  /* 163840 B */

#define INV254 (1.0f/254.0f)
#define QSC    (1.0f/127.0f)

// ---------------------------------------------------------------------------
// Scratch (static __device__ arrays; no allocation anywhere)
// ---------------------------------------------------------------------------
__device__ __align__(16) int8_t g_x0[BATCH*KXP],   g_x1[BATCH*KXP];
__device__ __align__(16) int8_t g_hA0[BATCH*HDIM], g_hA1[BATCH*HDIM];
__device__ __align__(16) int8_t g_hB0[BATCH*HDIM], g_hB1[BATCH*HDIM];
__device__ __align__(16) int8_t g_u0[BATCH*HDIM],  g_u1[BATCH*HDIM];
__device__ __align__(16) int8_t g_v0[BATCH*ADIM],  g_v1[BATCH*ADIM];
__device__ __align__(16) float  g_hf[BATCH*HDIM];
__device__ __align__(16) float  g_vf[BATCH*ADIM];
__device__ __align__(16) float  g_dh[BATCH*ADIM];
__device__ __align__(16) float  g_dloc[BATCH*ZDIM];

__device__ __align__(16) int8_t g_W0q0[HDIM*KXP],      g_W0q1[HDIM*KXP];
__device__ __align__(16) int8_t g_W1q0[RB*HDIM*HDIM],  g_W1q1[RB*HDIM*HDIM];
__device__ __align__(16) int8_t g_W2q0[RB*HDIM*HDIM],  g_W2q1[RB*HDIM*HDIM];
__device__ __align__(16) int8_t g_Wfq0[SDIM*HDIM],     g_Wfq1[SDIM*HDIM];
__device__ __align__(16) int8_t g_TIq0[ADIM*ADIM],     g_TIq1[ADIM*ADIM];
__device__ __align__(16) int8_t g_TOq0[ADIM*ADIM],     g_TOq1[ADIM*ADIM];

__device__ float g_sW0[HDIM], g_sW1[RB*HDIM], g_sW2[RB*HDIM];
__device__ float g_sWf[SDIM], g_sTI[ADIM], g_sTO[ADIM];
__device__ float g_sx[BATCH], g_shA[BATCH], g_sv[BATCH];

// ---------------------------------------------------------------------------
// Helpers
// ---------------------------------------------------------------------------
__device__ __forceinline__ float tanh_fast(float x) {
    float e = __expf(2.0f * x);
    return 1.0f - __fdividef(2.0f, e + 1.0f);   // NaN-safe
}
__device__ __forceinline__ uint32_t smem_u32(const void* p) {
    uint32_t a;
    asm("{ .reg .u64 t; cvta.to.shared.u64 t, %1; cvt.u32.u64 %0, t; }" : "=r"(a) : "l"(p));
    return a;
}
__device__ __forceinline__ void ldm4(unsigned r[4], uint32_t addr) {
    asm volatile("ldmatrix.sync.aligned.m8n8.x4.shared.b16 {%0,%1,%2,%3}, [%4];"
                 : "=r"(r[0]), "=r"(r[1]), "=r"(r[2]), "=r"(r[3]) : "r"(addr));
}
__device__ __forceinline__ void ldm2(unsigned r[2], uint32_t addr) {
    asm volatile("ldmatrix.sync.aligned.m8n8.x2.shared.b16 {%0,%1}, [%2];"
                 : "=r"(r[0]), "=r"(r[1]) : "r"(addr));
}
__device__ __forceinline__ void mma_s8(int c[4], const unsigned a[4], const unsigned b[2]) {
    asm volatile(
        "mma.sync.aligned.m16n8k32.row.col.s32.s8.s8.s32 "
        "{%0,%1,%2,%3}, {%4,%5,%6,%7}, {%8,%9}, {%0,%1,%2,%3};"
        : "+r"(c[0]), "+r"(c[1]), "+r"(c[2]), "+r"(c[3])
        : "r"(a[0]), "r"(a[1]), "r"(a[2]), "r"(a[3]), "r"(b[0]), "r"(b[1]));
}
__device__ __forceinline__ void cpa16(uint32_t dst, const void* src, unsigned n) {
    asm volatile("cp.async.cg.shared.global [%0], [%1], 16, %2;"
                 :: "r"(dst), "l"(src), "r"(n));
}
#define CP_COMMIT() asm volatile("cp.async.commit_group;" ::: "memory")
#define CP_WAIT2()  asm volatile("cp.async.wait_group 2;"  ::: "memory")
#define CP_WAIT0()  asm volatile("cp.async.wait_group 0;"  ::: "memory")

// two-level int8 quantization of q in [-127, 127]
__device__ __forceinline__ void quant2(float q, int8_t& o0, int8_t& o1) {
    int a0 = __float2int_rn(q);
    int a1 = __float2int_rn((q - (float)a0) * 254.0f);
    o0 = (int8_t)a0;
    o1 = (int8_t)a1;
}

// ---------------------------------------------------------------------------
// int8 GEMM: C(MxN) = act( A @ B^T + bias [+ AD] )
// A = sA[m]*(A0 + A1/254), B = sB[n]*(B0 + B1/254); exact s32 P0, P1(cross).
// a1*b1 term dropped (<= ~1.5e-5 relative).
// Output: f32 (Cf) or 2-level int8 with fixed scale 1/127 (tanh path).
// ---------------------------------------------------------------------------
__global__ void __launch_bounds__(256, 1)
gemm_i8(const int8_t* __restrict__ A0g, const int8_t* __restrict__ A1g,
        const float* __restrict__ sA, int lda,
        const int8_t* __restrict__ B0g, const int8_t* __restrict__ B1g,
        const float* __restrict__ sB, int ldb,
        const float* __restrict__ bias,
        const int8_t* __restrict__ AD0, const int8_t* __restrict__ AD1,
        const float* __restrict__ sAD, int ldad,
        float* __restrict__ Cf, int8_t* __restrict__ Cq0, int8_t* __restrict__ Cq1,
        int ldc, int N, int K, int epi)
{
    extern __shared__ __align__(16) char smem[];
    const uint32_t sb = smem_u32(smem);

    const int tid    = threadIdx.x;
    const int lane   = tid & 31;
    const int wid    = tid >> 5;
    const int warpM  = wid >> 2;        // 0..1
    const int warpN  = wid & 3;         // 0..3
    const int blockM = blockIdx.y * 128;
    const int blockN = blockIdx.x * 128;

    // ---- staging: thread t handles rows r0 and r0+64, 16B unit q0 ----
    const int r0 = tid >> 2, q0 = tid & 3;
    const int8_t* pA0a = A0g + (size_t)(blockM + r0) * lda + q0 * 16;
    const int8_t* pA1a = A1g + (size_t)(blockM + r0) * lda + q0 * 16;
    const int8_t* pA0b = pA0a + (size_t)64 * lda;
    const int8_t* pA1b = pA1a + (size_t)64 * lda;
    const int nGa = blockN + r0, nGb = blockN + r0 + 64;
    const unsigned szA = (nGa < N) ? 16u : 0u;   // reuse name; A rows always valid
    const unsigned szBa = (nGa < N) ? 16u : 0u;
    const unsigned szBb = (nGb < N) ? 16u : 0u;
    const int8_t* pB0a = B0g + (size_t)(nGa < N ? nGa : 0) * ldb + q0 * 16;
    const int8_t* pB1a = B1g + (size_t)(nGa < N ? nGa : 0) * ldb + q0 * 16;
    const int8_t* pB0b = B0g + (size_t)(nGb < N ? nGb : 0) * ldb + q0 * 16;
    const int8_t* pB1b = B1g + (size_t)(nGb < N ? nGb : 0) * ldb + q0 * 16;
    (void)szA;

    const uint32_t dRa = (uint32_t)(r0 * RSTR + q0 * 16);
    const uint32_t dRb = dRa + 64 * RSTR;

    // ---- ldmatrix row/col bases (within a stage level) ----
    const uint32_t aRow = (uint32_t)((warpM * 64 + (lane & 15)) * RSTR + (lane >> 4) * 16);
    const uint32_t bRow = (uint32_t)((warpN * 32 + (lane & 7)) * RSTR + ((lane >> 3) & 1) * 16);

    int P0[4][4][4], P1[4][4][4];
    #pragma unroll
    for (int mt = 0; mt < 4; ++mt)
        #pragma unroll
        for (int nt = 0; nt < 4; ++nt)
            #pragma unroll
            for (int i = 0; i < 4; ++i) { P0[mt][nt][i] = 0; P1[mt][nt][i] = 0; }

    const int nk = K / KC;

    auto stage_copy = [&](int slot, int k0) {
        const uint32_t so = sb + (uint32_t)(slot * STG_SZ);
        cpa16(so + dRa,          pA0a + k0, 16u);
        cpa16(so + dRb,          pA0b + k0, 16u);
        cpa16(so + LV + dRa,     pA1a + k0, 16u);
        cpa16(so + LV + dRb,     pA1b + k0, 16u);
        cpa16(so + 2*LV + dRa,   pB0a + k0, szBa);
        cpa16(so + 2*LV + dRb,   pB0b + k0, szBb);
        cpa16(so + 3*LV + dRa,   pB1a + k0, szBa);
        cpa16(so + 3*LV + dRb,   pB1b + k0, szBb);
    };

    stage_copy(0, 0);      CP_COMMIT();
    stage_copy(1, KC);     CP_COMMIT();
    stage_copy(2, 2 * KC); CP_COMMIT();

    int cs = 0, ns = 3;
    for (int kt = 0; kt < nk; ++kt) {
        CP_WAIT2();
        __syncthreads();

        if (kt + 3 < nk) stage_copy(ns, (kt + 3) * KC);
        CP_COMMIT();

        const uint32_t so = sb + (uint32_t)(cs * STG_SZ);
        #pragma unroll
        for (int ks = 0; ks < 2; ++ks) {
            unsigned A0f[4][4], A1f[4][4];
            #pragma unroll
            for (int mt = 0; mt < 4; ++mt) {
                const uint32_t ao = aRow + (uint32_t)(mt * 16 * RSTR + ks * 32);
                ldm4(A0f[mt], so + ao);
                ldm4(A1f[mt], so + LV + ao);
            }
            #pragma unroll
            for (int nt = 0; nt < 4; ++nt) {
                unsigned B0f[2], B1f[2];
                const uint32_t bo = bRow + (uint32_t)(nt * 8 * RSTR + ks * 32);
                ldm2(B0f, so + 2*LV + bo);
                ldm2(B1f, so + 3*LV + bo);
                #pragma unroll
                for (int mt = 0; mt < 4; ++mt) {
                    mma_s8(P0[mt][nt], A0f[mt], B0f);
                    mma_s8(P1[mt][nt], A0f[mt], B1f);
                    mma_s8(P1[mt][nt], A1f[mt], B0f);
                }
            }
        }
        cs = (cs + 1) & 3;
        ns = (ns + 1) & 3;
    }
    CP_WAIT0();

    // ---- epilogue ----
    const int g = lane >> 2, q2 = lane & 3;
    #pragma unroll
    for (int mt = 0; mt < 4; ++mt) {
        #pragma unroll
        for (int nt = 0; nt < 4; ++nt) {
            const int row0 = blockM + warpM * 64 + mt * 16 + g;
            const int col  = blockN + warpN * 32 + nt * 8 + q2 * 2;
            const bool c0 = col < N, c1 = (col + 1) < N;
            const float sb0 = c0 ? sB[col] : 0.0f;
            const float sb1 = c1 ? sB[col + 1] : 0.0f;
            const float b0v = c0 ? bias[col] : 0.0f;
            const float b1v = c1 ? bias[col + 1] : 0.0f;
            #pragma unroll
            for (int rr = 0; rr < 2; ++rr) {
                const int r = row0 + rr * 8;
                const float sa = sA ? sA[r] : QSC;
                float v0 = sa * sb0 * ((float)P0[mt][nt][rr*2+0]
                                       + (float)P1[mt][nt][rr*2+0] * INV254) + b0v;
                float v1 = sa * sb1 * ((float)P0[mt][nt][rr*2+1]
                                       + (float)P1[mt][nt][rr*2+1] * INV254) + b1v;
                if (AD0) {
                    const float sad = sAD ? sAD[r] : QSC;
                    const size_t o = (size_t)r * ldad + col;
                    if (c0) v0 += sad * ((float)AD0[o]     + (float)AD1[o]     * INV254);
                    if (c1) v1 += sad * ((float)AD0[o + 1] + (float)AD1[o + 1] * INV254);
                }
                if (epi == EPI_RELU)      { v0 = fmaxf(v0, 0.0f); v1 = fmaxf(v1, 0.0f); }
                else if (epi == EPI_TANH) { v0 = tanh_fast(v0);   v1 = tanh_fast(v1);   }
                const size_t oc = (size_t)r * ldc + col;
                if (Cf) {
                    if (c0) Cf[oc]     = v0;
                    if (c1) Cf[oc + 1] = v1;
                } else {
                    int8_t a0, a1, b0q, b1q;
                    quant2(v0 * 127.0f, a0, a1);
                    quant2(v1 * 127.0f, b0q, b1q);
                    char2 p0; p0.x = a0; p0.y = b0q;
                    char2 p1; p1.x = a1; p1.y = b1q;
                    *(char2*)(Cq0 + oc) = p0;
                    *(char2*)(Cq1 + oc) = p1;
                }
            }
        }
    }
}

// ---------------------------------------------------------------------------
// Per-row 2-level int8 quantization (one block per row)
// ---------------------------------------------------------------------------
__device__ void quant_row(const float* __restrict__ src, int srcK,
                          int8_t* __restrict__ d0, int8_t* __restrict__ d1,
                          float* __restrict__ sOut, int dstK)
{
    __shared__ float red[8];
    const int tid = threadIdx.x;
    float mx = 0.0f;
    for (int c = tid; c < srcK; c += 256) mx = fmaxf(mx, fabsf(src[c]));
    #pragma unroll
    for (int o = 16; o > 0; o >>= 1) mx = fmaxf(mx, __shfl_xor_sync(0xffffffffu, mx, o));
    if ((tid & 31) == 0) red[tid >> 5] = mx;
    __syncthreads();
    if (tid < 8) {
        float m = red[tid];
        #pragma unroll
        for (int o = 4; o > 0; o >>= 1) m = fmaxf(m, __shfl_xor_sync(0xffu, m, o));
        if (tid == 0) red[0] = fmaxf(m, 1e-20f);
    }
    __syncthreads();
    const float inv = 127.0f / red[0];
    for (int c = tid; c < dstK; c += 256) {
        float w = (c < srcK) ? src[c] : 0.0f;
        int8_t a0, a1;
        quant2(w * inv, a0, a1);
        d0[c] = a0; d1[c] = a1;
    }
    if (tid == 0 && sOut) *sOut = red[0] * QSC;
}

__global__ void qw_pair_kernel(const float* __restrict__ rW1, const float* __restrict__ rW2)
{
    const int r = blockIdx.x;
    if (blockIdx.y == 0)
        quant_row(rW1 + (size_t)r * HDIM, HDIM, g_W1q0 + (size_t)r * HDIM,
                  g_W1q1 + (size_t)r * HDIM, g_sW1 + r, HDIM);
    else
        quant_row(rW2 + (size_t)r * HDIM, HDIM, g_W2q0 + (size_t)r * HDIM,
                  g_W2q1 + (size_t)r * HDIM, g_sW2 + r, HDIM);
}

__global__ void qmisc_kernel(const float* __restrict__ Wf, const float* __restrict__ ta_in_w,
                             const float* __restrict__ ta_out_w, const float* __restrict__ W0)
{
    const int r = blockIdx.x;
    if (r < SDIM) {
        quant_row(Wf + (size_t)r * HDIM, HDIM, g_Wfq0 + (size_t)r * HDIM,
                  g_Wfq1 + (size_t)r * HDIM, g_sWf + r, HDIM);
    } else if (r < SDIM + ADIM) {
        const int r2 = r - SDIM;
        quant_row(ta_in_w + (size_t)(2 * ADIM + r2) * ADIM, ADIM,
                  g_TIq0 + (size_t)r2 * ADIM, g_TIq1 + (size_t)r2 * ADIM, g_sTI + r2, ADIM);
    } else if (r < SDIM + 2 * ADIM) {
        const int r3 = r - SDIM - ADIM;
        quant_row(ta_out_w + (size_t)r3 * ADIM, ADIM,
                  g_TOq0 + (size_t)r3 * ADIM, g_TOq1 + (size_t)r3 * ADIM, g_sTO + r3, ADIM);
    } else {
        const int r4 = r - SDIM - 2 * ADIM;
        quant_row(W0 + (size_t)r4 * (SDIM + 2), SDIM + 2,
                  g_W0q0 + (size_t)r4 * KXP, g_W0q1 + (size_t)r4 * KXP, g_sW0 + r4, KXP);
    }
}

// build + quantize x per row: [state(268), sin, cos, 0-pad -> 320]
__global__ void qx_kernel(const float* __restrict__ state, const float* __restrict__ t)
{
    __shared__ float red[8];
    __shared__ float sc[2];
    const int b = blockIdx.x;
    const int tid = threadIdx.x;
    if (tid == 0) {
        float ang = t[0] * 0.26179938779914943654f;
        sc[0] = sinf(ang); sc[1] = cosf(ang);
    }
    __syncthreads();
    float mx = 0.0f;
    for (int c = tid; c < KXP; c += 256) {
        float v = 0.0f;
        if (c < SDIM) v = state[(size_t)b * SDIM + c];
        else if (c == SDIM) v = sc[0];
        else if (c == SDIM + 1) v = sc[1];
        mx = fmaxf(mx, fabsf(v));
    }
    #pragma unroll
    for (int o = 16; o > 0; o >>= 1) mx = fmaxf(mx, __shfl_xor_sync(0xffffffffu, mx, o));
    if ((tid & 31) == 0) red[tid >> 5] = mx;
    __syncthreads();
    if (tid < 8) {
        float m = red[tid];
        #pragma unroll
        for (int o = 4; o > 0; o >>= 1) m = fmaxf(m, __shfl_xor_sync(0xffu, m, o));
        if (tid == 0) red[0] = fmaxf(m, 1e-20f);
    }
    __syncthreads();
    const float m = red[0];
    const float inv = 127.0f / m;
    for (int c = tid; c < KXP; c += 256) {
        float v = 0.0f;
        if (c < SDIM) v = state[(size_t)b * SDIM + c];
        else if (c == SDIM) v = sc[0];
        else if (c == SDIM + 1) v = sc[1];
        int8_t a0, a1;
        quant2(v * inv, a0, a1);
        g_x0[(size_t)b * KXP + c] = a0;
        g_x1[(size_t)b * KXP + c] = a1;
    }
    if (tid == 0) g_sx[b] = m * QSC;
}

__global__ void rowquant_kernel(const float* __restrict__ src, int width,
                                int8_t* __restrict__ d0, int8_t* __restrict__ d1,
                                float* __restrict__ sOut)
{
    const int r = blockIdx.x;
    quant_row(src + (size_t)r * width, width, d0 + (size_t)r * width,
              d1 + (size_t)r * width, sOut + r, width);
}

// ---------------------------------------------------------------------------
// Tiny loc path (exact fp32)
// ---------------------------------------------------------------------------
__global__ void loc_kernel(const float* __restrict__ state,
                           const float* __restrict__ loc_proj_w, const float* __restrict__ loc_proj_b,
                           const float* __restrict__ lp_in_w,    const float* __restrict__ lp_in_b,
                           const float* __restrict__ lp_out_w,   const float* __restrict__ lp_out_b,
                           const float* __restrict__ loc_back_w, const float* __restrict__ loc_back_b,
                           float* __restrict__ dloc)
{
    int b = blockIdx.x * blockDim.x + threadIdx.x;
    if (b >= BATCH) return;
    float loc[ZDIM];
    #pragma unroll
    for (int z = 0; z < ZDIM; ++z) loc[z] = state[b * SDIM + ADIM + z];
    float lp[EDIM];
    #pragma unroll
    for (int e = 0; e < EDIM; ++e) {
        float s = loc_proj_b[e];
        #pragma unroll
        for (int z = 0; z < ZDIM; ++z) s += loc_proj_w[e * ZDIM + z] * loc[z];
        lp[e] = s;
    }
    float v[EDIM];
    #pragma unroll
    for (int e = 0; e < EDIM; ++e) {
        float s = lp_in_b[2 * EDIM + e];
        #pragma unroll
        for (int j = 0; j < EDIM; ++j) s += lp_in_w[(2 * EDIM + e) * EDIM + j] * lp[j];
        v[e] = s;
    }
    float d[EDIM];
    #pragma unroll
    for (int e = 0; e < EDIM; ++e) {
        float s = lp_out_b[e];
        #pragma unroll
        for (int j = 0; j < EDIM; ++j) s += lp_out_w[e * EDIM + j] * v[j];
        d[e] = s - lp[e];
    }
    #pragma unroll
    for (int z = 0; z < ZDIM; ++z) {
        float s = loc_back_b[z];
        #pragma unroll
        for (int e = 0; e < EDIM; ++e) s += loc_back_w[z * EDIM + e] * d[e];
        dloc[b * ZDIM + z] = s;
    }
}

__global__ void combine_kernel(float* __restrict__ out,
                               const float* __restrict__ state,
                               const float* __restrict__ dh,
                               const float* __restrict__ dloc)
{
    int i = blockIdx.x * blockDim.x + threadIdx.x;
    if (i >= BATCH * SDIM) return;
    int b = i / SDIM, j = i % SDIM;
    float o = out[i];
    if (j < ADIM)              o += 0.1f * (dh[b * ADIM + j] - state[i]);
    else if (j < ADIM + ZDIM)  o += 0.1f * dloc[b * ZDIM + (j - ADIM)];
    out[i] = o;
}

// ---------------------------------------------------------------------------
// Launch
// ---------------------------------------------------------------------------
extern "C" void kernel_launch(void* const* d_in, const int* in_sizes, int n_in,
                              void* d_out, int out_size)
{
    const float* t          = (const float*)d_in[0];
    const float* state      = (const float*)d_in[1];
    const float* W0         = (const float*)d_in[2];
    const float* b0         = (const float*)d_in[3];
    const float* rW1        = (const float*)d_in[4];
    const float* rb1        = (const float*)d_in[5];
    const float* rW2        = (const float*)d_in[6];
    const float* rb2        = (const float*)d_in[7];
    const float* Wf         = (const float*)d_in[8];
    const float* bf_        = (const float*)d_in[9];
    const float* lp_in_w    = (const float*)d_in[10];
    const float* lp_in_b    = (const float*)d_in[11];
    const float* lp_out_w   = (const float*)d_in[12];
    const float* lp_out_b   = (const float*)d_in[13];
    const float* ta_in_w    = (const float*)d_in[14];
    const float* ta_in_b    = (const float*)d_in[15];
    const float* ta_out_w   = (const float*)d_in[16];
    const float* ta_out_b   = (const float*)d_in[17];
    const float* loc_proj_w = (const float*)d_in[18];
    const float* loc_proj_b = (const float*)d_in[19];
    const float* loc_back_w = (const float*)d_in[20];
    const float* loc_back_b = (const float*)d_in[21];
    float* out = (float*)d_out;

    int8_t *x0,*x1,*hA0,*hA1,*hB0,*hB1,*u0,*u1,*v0,*v1;
    int8_t *W0q0,*W0q1,*W1q0,*W1q1,*W2q0,*W2q1,*Wfq0,*Wfq1,*TIq0,*TIq1,*TOq0,*TOq1;
    float *hf,*vf,*dh,*dloc,*sW0,*sW1,*sW2,*sWf,*sTI,*sTO,*sx,*shA,*sv;
    cudaGetSymbolAddress((void**)&x0, g_x0);   cudaGetSymbolAddress((void**)&x1, g_x1);
    cudaGetSymbolAddress((void**)&hA0, g_hA0); cudaGetSymbolAddress((void**)&hA1, g_hA1);
    cudaGetSymbolAddress((void**)&hB0, g_hB0); cudaGetSymbolAddress((void**)&hB1, g_hB1);
    cudaGetSymbolAddress((void**)&u0, g_u0);   cudaGetSymbolAddress((void**)&u1, g_u1);
    cudaGetSymbolAddress((void**)&v0, g_v0);   cudaGetSymbolAddress((void**)&v1, g_v1);
    cudaGetSymbolAddress((void**)&hf, g_hf);   cudaGetSymbolAddress((void**)&vf, g_vf);
    cudaGetSymbolAddress((void**)&dh, g_dh);   cudaGetSymbolAddress((void**)&dloc, g_dloc);
    cudaGetSymbolAddress((void**)&W0q0, g_W0q0); cudaGetSymbolAddress((void**)&W0q1, g_W0q1);
    cudaGetSymbolAddress((void**)&W1q0, g_W1q0); cudaGetSymbolAddress((void**)&W1q1, g_W1q1);
    cudaGetSymbolAddress((void**)&W2q0, g_W2q0); cudaGetSymbolAddress((void**)&W2q1, g_W2q1);
    cudaGetSymbolAddress((void**)&Wfq0, g_Wfq0); cudaGetSymbolAddress((void**)&Wfq1, g_Wfq1);
    cudaGetSymbolAddress((void**)&TIq0, g_TIq0); cudaGetSymbolAddress((void**)&TIq1, g_TIq1);
    cudaGetSymbolAddress((void**)&TOq0, g_TOq0); cudaGetSymbolAddress((void**)&TOq1, g_TOq1);
    cudaGetSymbolAddress((void**)&sW0, g_sW0); cudaGetSymbolAddress((void**)&sW1, g_sW1);
    cudaGetSymbolAddress((void**)&sW2, g_sW2); cudaGetSymbolAddress((void**)&sWf, g_sWf);
    cudaGetSymbolAddress((void**)&sTI, g_sTI); cudaGetSymbolAddress((void**)&sTO, g_sTO);
    cudaGetSymbolAddress((void**)&sx, g_sx);   cudaGetSymbolAddress((void**)&shA, g_shA);
    cudaGetSymbolAddress((void**)&sv, g_sv);

    cudaFuncSetAttribute(gemm_i8, cudaFuncAttributeMaxDynamicSharedMemorySize, SMEM_DYN);

    // --- prologue (3 launches; ncu -s 5 lands on residual GEMM) ---
    qw_pair_kernel<<<dim3(RB * HDIM, 2), 256>>>(rW1, rW2);
    qmisc_kernel<<<SDIM + 2 * ADIM + HDIM, 256>>>(Wf, ta_in_w, ta_out_w, W0);
    qx_kernel<<<BATCH, 256>>>(state, t);

    dim3 blk(256);
    dim3 gH(HDIM / 128, BATCH / 128);           // (8, 64)

    // h = relu(x @ W0^T + b0) -> f32, then per-row quantize
    gemm_i8<<<gH, blk, SMEM_DYN>>>(x0, x1, sx, KXP, W0q0, W0q1, sW0, KXP, b0,
                                   nullptr, nullptr, nullptr, 0,
                                   hf, nullptr, nullptr, HDIM, HDIM, KXP, EPI_RELU);
    rowquant_kernel<<<BATCH, 256>>>(hf, HDIM, hA0, hA1, shA);

    int8_t *c0 = hA0, *c1 = hA1, *n0 = hB0, *n1 = hB1;
    float* csp = shA;   // per-row scale ptr for current h (null => const 1/127)
    for (int i = 0; i < RB; ++i) {
        const size_t wo = (size_t)i * HDIM * HDIM;
        gemm_i8<<<gH, blk, SMEM_DYN>>>(c0, c1, csp, HDIM,
                                       W1q0 + wo, W1q1 + wo, sW1 + i * HDIM, HDIM,
                                       rb1 + i * HDIM,
                                       nullptr, nullptr, nullptr, 0,
                                       nullptr, u0, u1, HDIM, HDIM, HDIM, EPI_TANH);
        gemm_i8<<<gH, blk, SMEM_DYN>>>(u0, u1, nullptr, HDIM,
                                       W2q0 + wo, W2q1 + wo, sW2 + i * HDIM, HDIM,
                                       rb2 + i * HDIM,
                                       c0, c1, csp, HDIM,
                                       nullptr, n0, n1, HDIM, HDIM, HDIM, EPI_TANH);
        int8_t* s0 = c0; c0 = n0; n0 = s0;
        int8_t* s1 = c1; c1 = n1; n1 = s1;
        csp = nullptr;   // tanh outputs use const scale
    }

    // core = h @ Wf^T + bf -> f32 out
    dim3 gF(CDIV(SDIM, 128), BATCH / 128);      // (3, 64)
    gemm_i8<<<gF, blk, SMEM_DYN>>>(c0, c1, csp, HDIM, Wfq0, Wfq1, sWf, HDIM, bf_,
                                   nullptr, nullptr, nullptr, 0,
                                   out, nullptr, nullptr, SDIM, SDIM, HDIM, EPI_NONE);

    // --- independent side path (h_part = first 256 cols of x) ---
    dim3 gT(ADIM / 128, BATCH / 128);           // (2, 64)
    gemm_i8<<<gT, blk, SMEM_DYN>>>(x0, x1, sx, KXP, TIq0, TIq1, sTI, ADIM,
                                   ta_in_b + 2 * ADIM,
                                   nullptr, nullptr, nullptr, 0,
                                   vf, nullptr, nullptr, ADIM, ADIM, ADIM, EPI_NONE);
    rowquant_kernel<<<BATCH, 256>>>(vf, ADIM, v0, v1, sv);
    gemm_i8<<<gT, blk, SMEM_DYN>>>(v0, v1, sv, ADIM, TOq0, TOq1, sTO, ADIM,
                                   ta_out_b,
                                   nullptr, nullptr, nullptr, 0,
                                   dh, nullptr, nullptr, ADIM, ADIM, ADIM, EPI_NONE);
    loc_kernel<<<CDIV(BATCH, 256), 256>>>(state, loc_proj_w, loc_proj_b,
                                          lp_in_w, lp_in_b, lp_out_w, lp_out_b,
                                          loc_back_w, loc_back_b, dloc);

    combine_kernel<<<CDIV(BATCH * SDIM, 256), 256>>>(out, state, dh, dloc);
}

// round 9
// speedup vs baseline: 5.7659x; 5.7659x over previous
#include <cuda_runtime.h>
#include <cuda_fp16.h>
#include <cstdint>
#include <math.h>

#define BATCH 8192
#define SDIM  268
#define HDIM  1024
#define RB    8
#define ADIM  256
#define ZDIM  8
#define EDIM  4
#define KX    288   /* 270 padded to multiple of 32 */

#define CDIV(a,b) (((a)+(b)-1)/(b))
#define EPI_NONE 0
#define EPI_RELU 1
#define EPI_TANH 2

// GEMM: CTA 128x128, 8 warps (2M x 4N), warp tile 64x32, K chunk 32
#define KC     32
#define RSTR   80               /* 64B data + 16B pad per row */
#define OFF_B  10240            /* A level = 128*80 */
#define STG_SZ 20480
#define NSTAGE 4
#define SMEM_DYN (NSTAGE*STG_SZ)   /* 81920 B */

// ---------------------------------------------------------------------------
// Scratch (static __device__ arrays; no allocation anywhere)
// ---------------------------------------------------------------------------
__device__ __align__(16) __half g_x [BATCH*KX];
__device__ __align__(16) __half g_hA[BATCH*HDIM];
__device__ __align__(16) __half g_hB[BATCH*HDIM];
__device__ __align__(16) __half g_u [BATCH*HDIM];
__device__ __align__(16) __half g_v [BATCH*ADIM];
__device__ __align__(16) float  g_dh[BATCH*ADIM];
__device__ __align__(16) float  g_dloc[BATCH*ZDIM];

__device__ __align__(16) __half g_W0[HDIM*KX];
__device__ __align__(16) __half g_W1[RB*HDIM*HDIM];
__device__ __align__(16) __half g_W2[RB*HDIM*HDIM];
__device__ __align__(16) __half g_Wf[SDIM*HDIM];
__device__ __align__(16) __half g_TI[ADIM*ADIM];
__device__ __align__(16) __half g_TO[ADIM*ADIM];

// ---------------------------------------------------------------------------
// Helpers
// ---------------------------------------------------------------------------
__device__ __forceinline__ float tanh_fast(float x) {
    float e = __expf(2.0f * x);
    return 1.0f - __fdividef(2.0f, e + 1.0f);   // NaN-safe
}
__device__ __forceinline__ uint32_t smem_u32(const void* p) {
    uint32_t a;
    asm("{ .reg .u64 t; cvta.to.shared.u64 t, %1; cvt.u32.u64 %0, t; }" : "=r"(a) : "l"(p));
    return a;
}
__device__ __forceinline__ void ldm4(unsigned r[4], uint32_t addr) {
    asm volatile("ldmatrix.sync.aligned.m8n8.x4.shared.b16 {%0,%1,%2,%3}, [%4];"
                 : "=r"(r[0]), "=r"(r[1]), "=r"(r[2]), "=r"(r[3]) : "r"(addr));
}
__device__ __forceinline__ void ldm2(unsigned r[2], uint32_t addr) {
    asm volatile("ldmatrix.sync.aligned.m8n8.x2.shared.b16 {%0,%1}, [%2];"
                 : "=r"(r[0]), "=r"(r[1]) : "r"(addr));
}
__device__ __forceinline__ void mma_f16(float c[4], const unsigned a[4], const unsigned b[2]) {
    asm volatile(
        "mma.sync.aligned.m16n8k16.row.col.f32.f16.f16.f32 "
        "{%0,%1,%2,%3}, {%4,%5,%6,%7}, {%8,%9}, {%0,%1,%2,%3};"
        : "+f"(c[0]), "+f"(c[1]), "+f"(c[2]), "+f"(c[3])
        : "r"(a[0]), "r"(a[1]), "r"(a[2]), "r"(a[3]), "r"(b[0]), "r"(b[1]));
}
__device__ __forceinline__ void cpa16(uint32_t dst, const void* src, unsigned n) {
    asm volatile("cp.async.cg.shared.global [%0], [%1], 16, %2;"
                 :: "r"(dst), "l"(src), "r"(n));
}
#define CP_COMMIT() asm volatile("cp.async.commit_group;" ::: "memory")
#define CP_WAIT2()  asm volatile("cp.async.wait_group 2;"  ::: "memory")
#define CP_WAIT0()  asm volatile("cp.async.wait_group 0;"  ::: "memory")

// ---------------------------------------------------------------------------
// fp16 GEMM: C(MxN) = act( A(MxK) @ B^T + bias [+ AD] )
// A, B, AD fp16; accumulate f32; output f32 (Cf) or fp16 (Ch).
// ---------------------------------------------------------------------------
__global__ void __launch_bounds__(256, 2)
gemm_f16(const __half* __restrict__ A, int lda,
         const __half* __restrict__ B, int ldb,
         const float* __restrict__ bias,
         const __half* __restrict__ AD, int ldad,
         float* __restrict__ Cf, __half* __restrict__ Ch,
         int ldc, int N, int K, int epi)
{
    extern __shared__ __align__(16) char smem[];
    const uint32_t sb = smem_u32(smem);

    const int tid    = threadIdx.x;
    const int lane   = tid & 31;
    const int wid    = tid >> 5;
    const int warpM  = wid >> 2;        // 0..1
    const int warpN  = wid & 3;         // 0..3
    const int blockM = blockIdx.y * 128;
    const int blockN = blockIdx.x * 128;

    // staging: thread handles rows r0 and r0+64, 16B unit q0 (K-chunk = 64B)
    const int r0 = tid >> 2, q0 = tid & 3;
    const __half* pAa = A + (size_t)(blockM + r0) * lda + q0 * 8;
    const __half* pAb = pAa + (size_t)64 * lda;
    const int nGa = blockN + r0, nGb = nGa + 64;
    const unsigned szBa = (nGa < N) ? 16u : 0u;
    const unsigned szBb = (nGb < N) ? 16u : 0u;
    const __half* pBa = B + (size_t)(nGa < N ? nGa : 0) * ldb + q0 * 8;
    const __half* pBb = B + (size_t)(nGb < N ? nGb : 0) * ldb + q0 * 8;
    const uint32_t dRa = (uint32_t)(r0 * RSTR + q0 * 16);
    const uint32_t dRb = dRa + 64 * RSTR;

    // ldmatrix bases within a stage
    const uint32_t aOffB = (uint32_t)((warpM * 64 + (lane & 15)) * RSTR + (lane >> 4) * 16);
    const uint32_t bOffB = (uint32_t)((warpN * 32 + (lane & 7)) * RSTR + ((lane >> 3) & 1) * 16);

    float acc[4][4][4];
    #pragma unroll
    for (int mt = 0; mt < 4; ++mt)
        #pragma unroll
        for (int nt = 0; nt < 4; ++nt)
            #pragma unroll
            for (int i = 0; i < 4; ++i) acc[mt][nt][i] = 0.0f;

    const int nk = K / KC;

    auto stage_copy = [&](int slot, int k0) {
        const uint32_t so = sb + (uint32_t)(slot * STG_SZ);
        cpa16(so + dRa,         pAa + k0, 16u);
        cpa16(so + dRb,         pAb + k0, 16u);
        cpa16(so + OFF_B + dRa, pBa + k0, szBa);
        cpa16(so + OFF_B + dRb, pBb + k0, szBb);
    };

    stage_copy(0, 0);                     CP_COMMIT();
    if (nk > 1) stage_copy(1, KC);        CP_COMMIT();
    if (nk > 2) stage_copy(2, 2 * KC);    CP_COMMIT();

    int cs = 0, ns = 3;
    for (int kt = 0; kt < nk; ++kt) {
        CP_WAIT2();
        __syncthreads();

        if (kt + 3 < nk) stage_copy(ns, (kt + 3) * KC);
        CP_COMMIT();

        const uint32_t so = sb + (uint32_t)(cs * STG_SZ);
        #pragma unroll
        for (int ks = 0; ks < 2; ++ks) {
            unsigned Af[4][4];
            #pragma unroll
            for (int mt = 0; mt < 4; ++mt)
                ldm4(Af[mt], so + aOffB + (uint32_t)(mt * 16 * RSTR + ks * 32));
            #pragma unroll
            for (int nt = 0; nt < 4; ++nt) {
                unsigned Bf[2];
                ldm2(Bf, so + OFF_B + bOffB + (uint32_t)(nt * 8 * RSTR + ks * 32));
                #pragma unroll
                for (int mt = 0; mt < 4; ++mt)
                    mma_f16(acc[mt][nt], Af[mt], Bf);
            }
        }
        cs = (cs + 1) & 3;
        ns = (ns + 1) & 3;
    }
    CP_WAIT0();

    // ---- epilogue ----
    const int g = lane >> 2, q = lane & 3;
    #pragma unroll
    for (int mt = 0; mt < 4; ++mt) {
        #pragma unroll
        for (int nt = 0; nt < 4; ++nt) {
            const int row0 = blockM + warpM * 64 + mt * 16 + g;
            const int col  = blockN + warpN * 32 + nt * 8 + q * 2;
            const bool c0 = col < N, c1 = (col + 1) < N;
            const float b0v = c0 ? bias[col] : 0.0f;
            const float b1v = c1 ? bias[col + 1] : 0.0f;
            #pragma unroll
            for (int rr = 0; rr < 2; ++rr) {
                const int r = row0 + rr * 8;
                float v0 = acc[mt][nt][rr * 2 + 0] + b0v;
                float v1 = acc[mt][nt][rr * 2 + 1] + b1v;
                if (AD) {
                    const size_t o = (size_t)r * ldad + col;
                    if (c0) v0 += __half2float(AD[o]);
                    if (c1) v1 += __half2float(AD[o + 1]);
                }
                if (epi == EPI_RELU)      { v0 = fmaxf(v0, 0.0f); v1 = fmaxf(v1, 0.0f); }
                else if (epi == EPI_TANH) { v0 = tanh_fast(v0);   v1 = tanh_fast(v1);   }
                const size_t oc = (size_t)r * ldc + col;
                if (Cf) {
                    if (c0) Cf[oc]     = v0;
                    if (c1) Cf[oc + 1] = v1;
                } else {
                    if (c0 && c1) {
                        *(__half2*)(Ch + oc) = __floats2half2_rn(v0, v1);
                    } else if (c0) {
                        Ch[oc] = __float2half_rn(v0);
                    }
                }
            }
        }
    }
}

// ---------------------------------------------------------------------------
// Prologue: one conversion kernel covering W1, W2, Wf, TI, TO (contiguous runs)
// ---------------------------------------------------------------------------
#define N_W1 (RB*HDIM*HDIM)
#define N_W2 (RB*HDIM*HDIM)
#define N_WF (SDIM*HDIM)
#define N_TT (ADIM*ADIM)
#define N_ALL (N_W1 + N_W2 + N_WF + N_TT + N_TT)

__global__ void conv_all_kernel(const float* __restrict__ rW1, const float* __restrict__ rW2,
                                const float* __restrict__ Wf,  const float* __restrict__ ta_in_w,
                                const float* __restrict__ ta_out_w)
{
    const int i4 = blockIdx.x * blockDim.x + threadIdx.x;
    const long long i = (long long)i4 * 4;
    if (i >= N_ALL) return;
    const float* src; __half* dst; long long off;
    if (i < N_W1)                         { src = rW1;                         dst = g_W1; off = i; }
    else if (i < N_W1 + N_W2)             { src = rW2;                         dst = g_W2; off = i - N_W1; }
    else if (i < N_W1 + N_W2 + N_WF)      { src = Wf;                          dst = g_Wf; off = i - N_W1 - N_W2; }
    else if (i < N_W1 + N_W2 + N_WF + N_TT) { src = ta_in_w + 2 * ADIM * ADIM; dst = g_TI; off = i - N_W1 - N_W2 - N_WF; }
    else                                  { src = ta_out_w;                    dst = g_TO; off = i - N_W1 - N_W2 - N_WF - N_TT; }
    float4 v = *(const float4*)(src + off);
    __half2* d = (__half2*)(dst + off);
    d[0] = __floats2half2_rn(v.x, v.y);
    d[1] = __floats2half2_rn(v.z, v.w);
}

__global__ void convW0_kernel(const float* __restrict__ W0)
{
    int i = blockIdx.x * blockDim.x + threadIdx.x;
    if (i >= HDIM * KX) return;
    int row = i / KX, c = i % KX;
    float v = (c < SDIM + 2) ? W0[row * (SDIM + 2) + c] : 0.0f;
    g_W0[i] = __float2half_rn(v);
}

__global__ void buildx_kernel(const float* __restrict__ state, const float* __restrict__ t)
{
    int i = blockIdx.x * blockDim.x + threadIdx.x;
    if (i >= BATCH * KX) return;
    int b = i / KX, c = i % KX;
    float v;
    if (c < SDIM) v = state[b * SDIM + c];
    else if (c == SDIM)     { float ang = t[0] * 0.26179938779914943654f; v = sinf(ang); }
    else if (c == SDIM + 1) { float ang = t[0] * 0.26179938779914943654f; v = cosf(ang); }
    else v = 0.0f;
    g_x[i] = __float2half_rn(v);
}

// ---------------------------------------------------------------------------
// Tiny loc path (exact fp32)
// ---------------------------------------------------------------------------
__global__ void loc_kernel(const float* __restrict__ state,
                           const float* __restrict__ loc_proj_w, const float* __restrict__ loc_proj_b,
                           const float* __restrict__ lp_in_w,    const float* __restrict__ lp_in_b,
                           const float* __restrict__ lp_out_w,   const float* __restrict__ lp_out_b,
                           const float* __restrict__ loc_back_w, const float* __restrict__ loc_back_b,
                           float* __restrict__ dloc)
{
    int b = blockIdx.x * blockDim.x + threadIdx.x;
    if (b >= BATCH) return;
    float loc[ZDIM];
    #pragma unroll
    for (int z = 0; z < ZDIM; ++z) loc[z] = state[b * SDIM + ADIM + z];
    float lp[EDIM];
    #pragma unroll
    for (int e = 0; e < EDIM; ++e) {
        float s = loc_proj_b[e];
        #pragma unroll
        for (int z = 0; z < ZDIM; ++z) s += loc_proj_w[e * ZDIM + z] * loc[z];
        lp[e] = s;
    }
    float v[EDIM];
    #pragma unroll
    for (int e = 0; e < EDIM; ++e) {
        float s = lp_in_b[2 * EDIM + e];
        #pragma unroll
        for (int j = 0; j < EDIM; ++j) s += lp_in_w[(2 * EDIM + e) * EDIM + j] * lp[j];
        v[e] = s;
    }
    float d[EDIM];
    #pragma unroll
    for (int e = 0; e < EDIM; ++e) {
        float s = lp_out_b[e];
        #pragma unroll
        for (int j = 0; j < EDIM; ++j) s += lp_out_w[e * EDIM + j] * v[j];
        d[e] = s - lp[e];
    }
    #pragma unroll
    for (int z = 0; z < ZDIM; ++z) {
        float s = loc_back_b[z];
        #pragma unroll
        for (int e = 0; e < EDIM; ++e) s += loc_back_w[z * EDIM + e] * d[e];
        dloc[b * ZDIM + z] = s;
    }
}

__global__ void combine_kernel(float* __restrict__ out,
                               const float* __restrict__ state,
                               const float* __restrict__ dh,
                               const float* __restrict__ dloc)
{
    int i = blockIdx.x * blockDim.x + threadIdx.x;
    if (i >= BATCH * SDIM) return;
    int b = i / SDIM, j = i % SDIM;
    float o = out[i];
    if (j < ADIM)              o += 0.1f * (dh[b * ADIM + j] - state[i]);
    else if (j < ADIM + ZDIM)  o += 0.1f * dloc[b * ZDIM + (j - ADIM)];
    out[i] = o;
}

// ---------------------------------------------------------------------------
// Launch
// ---------------------------------------------------------------------------
extern "C" void kernel_launch(void* const* d_in, const int* in_sizes, int n_in,
                              void* d_out, int out_size)
{
    const float* t          = (const float*)d_in[0];
    const float* state      = (const float*)d_in[1];
    const float* W0         = (const float*)d_in[2];
    const float* b0         = (const float*)d_in[3];
    const float* rW1        = (const float*)d_in[4];
    const float* rb1        = (const float*)d_in[5];
    const float* rW2        = (const float*)d_in[6];
    const float* rb2        = (const float*)d_in[7];
    const float* Wf         = (const float*)d_in[8];
    const float* bf_        = (const float*)d_in[9];
    const float* lp_in_w    = (const float*)d_in[10];
    const float* lp_in_b    = (const float*)d_in[11];
    const float* lp_out_w   = (const float*)d_in[12];
    const float* lp_out_b   = (const float*)d_in[13];
    const float* ta_in_w    = (const float*)d_in[14];
    const float* ta_in_b    = (const float*)d_in[15];
    const float* ta_out_w   = (const float*)d_in[16];
    const float* ta_out_b   = (const float*)d_in[17];
    const float* loc_proj_w = (const float*)d_in[18];
    const float* loc_proj_b = (const float*)d_in[19];
    const float* loc_back_w = (const float*)d_in[20];
    const float* loc_back_b = (const float*)d_in[21];
    float* out = (float*)d_out;

    __half *x, *hA, *hB, *u, *v;
    float *dh, *dloc;
    __half *W0h, *W1h, *W2h, *Wfh, *TIh, *TOh;
    cudaGetSymbolAddress((void**)&x,  g_x);
    cudaGetSymbolAddress((void**)&hA, g_hA);
    cudaGetSymbolAddress((void**)&hB, g_hB);
    cudaGetSymbolAddress((void**)&u,  g_u);
    cudaGetSymbolAddress((void**)&v,  g_v);
    cudaGetSymbolAddress((void**)&dh, g_dh);
    cudaGetSymbolAddress((void**)&dloc, g_dloc);
    cudaGetSymbolAddress((void**)&W0h, g_W0);
    cudaGetSymbolAddress((void**)&W1h, g_W1);
    cudaGetSymbolAddress((void**)&W2h, g_W2);
    cudaGetSymbolAddress((void**)&Wfh, g_Wf);
    cudaGetSymbolAddress((void**)&TIh, g_TI);
    cudaGetSymbolAddress((void**)&TOh, g_TO);

    cudaFuncSetAttribute(gemm_f16, cudaFuncAttributeMaxDynamicSharedMemorySize, SMEM_DYN);

    // --- prologue: fp16 conversions (3 launches) ---
    conv_all_kernel<<<CDIV(N_ALL / 4, 256), 256>>>(rW1, rW2, Wf, ta_in_w, ta_out_w);
    convW0_kernel<<<CDIV(HDIM * KX, 256), 256>>>(W0);
    buildx_kernel<<<CDIV(BATCH * KX, 256), 256>>>(state, t);

    // --- main chain ---
    dim3 blk(256);
    dim3 gH(HDIM / 128, BATCH / 128);           // (8, 64)

    // h = relu(x @ W0^T + b0)
    gemm_f16<<<gH, blk, SMEM_DYN>>>(x, KX, W0h, KX, b0, nullptr, 0,
                                    nullptr, hA, HDIM, HDIM, KX, EPI_RELU);

    __half *hc = hA, *hn = hB;
    for (int i = 0; i < RB; ++i) {
        const size_t wo = (size_t)i * HDIM * HDIM;
        // u = tanh(h @ W1^T + b1)
        gemm_f16<<<gH, blk, SMEM_DYN>>>(hc, HDIM, W1h + wo, HDIM, rb1 + i * HDIM,
                                        nullptr, 0,
                                        nullptr, u, HDIM, HDIM, HDIM, EPI_TANH);
        // h' = tanh(u @ W2^T + b2 + h)
        gemm_f16<<<gH, blk, SMEM_DYN>>>(u, HDIM, W2h + wo, HDIM, rb2 + i * HDIM,
                                        hc, HDIM,
                                        nullptr, hn, HDIM, HDIM, HDIM, EPI_TANH);
        __half* tmp = hc; hc = hn; hn = tmp;
    }

    // core = h @ Wf^T + bf -> f32 out
    dim3 gF(CDIV(SDIM, 128), BATCH / 128);      // (3, 64)
    gemm_f16<<<gF, blk, SMEM_DYN>>>(hc, HDIM, Wfh, HDIM, bf_, nullptr, 0,
                                    out, nullptr, SDIM, SDIM, HDIM, EPI_NONE);

    // --- independent side path (h_part = first 256 cols of x) ---
    dim3 gT(ADIM / 128, BATCH / 128);           // (2, 64)
    gemm_f16<<<gT, blk, SMEM_DYN>>>(x, KX, TIh, ADIM, ta_in_b + 2 * ADIM, nullptr, 0,
                                    nullptr, v, ADIM, ADIM, ADIM, EPI_NONE);
    gemm_f16<<<gT, blk, SMEM_DYN>>>(v, ADIM, TOh, ADIM, ta_out_b, nullptr, 0,
                                    dh, nullptr, ADIM, ADIM, ADIM, EPI_NONE);
    loc_kernel<<<CDIV(BATCH, 256), 256>>>(state, loc_proj_w, loc_proj_b,
                                          lp_in_w, lp_in_b, lp_out_w, lp_out_b,
                                          loc_back_w, loc_back_b, dloc);

    combine_kernel<<<CDIV(BATCH * SDIM, 256), 256>>>(out, state, dh, dloc);
}